// round 5
// baseline (speedup 1.0000x reference)
#include <cuda_runtime.h>
#include <cuda_bf16.h>

// GraphGather / segment_sum:
//   out[b, :] = sum of feats[a, :] for membership[a] == b
// feats: [524288, 128] f32, membership: [524288] i32 (SORTED), out: [16384, 128] f32.
//
// R5: single-wave persistent layout.
//  - 4096 warps total (TPB=128, 1024 blocks), each owns a CONTIGUOUS
//    span of n_atoms/4096 = 128 rows (64 KB stream). Single wave,
//    <=7 blocks/SM, ~1% SM-level imbalance, zero wave transitions.
//  - accumulator carried across the whole span -> fewer boundary flushes.
//  - per 32-row chunk: 1 coalesced membership load + 4 batches of 8
//    unconditional LDG.E.128 (MLP_p1 = 8).
//  - flushes via atomicAdd (REDG); output zero-filled by float4 kernel.

#define N_FEAT 128
#define FEAT4 (N_FEAT / 4)       // 32 float4 per row
#define TPB 128
#define N_WARPS_TOTAL 4096
#define N_BLOCKS (N_WARPS_TOTAL / (TPB / 32))   // 1024

__global__ void gg_zero4_kernel(float4* __restrict__ out, int n4) {
    int i = blockIdx.x * blockDim.x + threadIdx.x;
    if (i < n4) out[i] = make_float4(0.f, 0.f, 0.f, 0.f);
}

__device__ __forceinline__ void gg_flush(float* __restrict__ out,
                                         int seg, int lane, const float4& acc) {
    float* o = out + (size_t)seg * N_FEAT + lane * 4;
    atomicAdd(o + 0, acc.x);
    atomicAdd(o + 1, acc.y);
    atomicAdd(o + 2, acc.z);
    atomicAdd(o + 3, acc.w);
}

__global__ __launch_bounds__(TPB)
void gg_segsum_kernel(const float4* __restrict__ feats,
                      const int* __restrict__ memb,
                      float* __restrict__ out,
                      int n_atoms, int rows_per_warp) {
    const int warp_id = (blockIdx.x * TPB + threadIdx.x) >> 5;
    const int lane = threadIdx.x & 31;
    const unsigned FULL = 0xFFFFFFFFu;

    int span0 = warp_id * rows_per_warp;
    if (span0 >= n_atoms) return;
    int span_end = min(span0 + rows_per_warp, n_atoms);

    float4 acc = make_float4(0.f, 0.f, 0.f, 0.f);
    int cur = memb[span0];   // warp-uniform scalar load (L1/L2 hit)

    // Walk the span in 32-row chunks; accumulator carries across chunks.
    for (int row0 = span0; row0 < span_end; row0 += 32) {
        const int nrows = min(32, span_end - row0);
        const float4* base = feats + (size_t)row0 * FEAT4 + lane;

        // One coalesced membership load covers the chunk.
        int mrow = row0 + lane;
        int mlane = memb[mrow < n_atoms ? mrow : (n_atoms - 1)];

        if (nrows == 32) {
            #pragma unroll
            for (int bt = 0; bt < 4; ++bt) {
                // 8 independent 128-bit loads, back-to-back (MLP_p1 = 8).
                float4 v[8];
                #pragma unroll
                for (int i = 0; i < 8; ++i)
                    v[i] = __ldcs(base + (size_t)(bt * 8 + i) * FEAT4);

                #pragma unroll
                for (int i = 0; i < 8; ++i) {
                    int m = __shfl_sync(FULL, mlane, bt * 8 + i);
                    if (m != cur) {          // rare: ~4 boundaries per span
                        gg_flush(out, cur, lane, acc);
                        acc = make_float4(0.f, 0.f, 0.f, 0.f);
                        cur = m;
                    }
                    acc.x += v[i].x; acc.y += v[i].y;
                    acc.z += v[i].z; acc.w += v[i].w;
                }
            }
        } else {
            for (int i = 0; i < nrows; ++i) {
                float4 v = __ldcs(base + (size_t)i * FEAT4);
                int m = __shfl_sync(FULL, mlane, i);
                if (m != cur) {
                    gg_flush(out, cur, lane, acc);
                    acc = make_float4(0.f, 0.f, 0.f, 0.f);
                    cur = m;
                }
                acc.x += v.x; acc.y += v.y; acc.z += v.z; acc.w += v.w;
            }
        }
    }

    gg_flush(out, cur, lane, acc);
}

extern "C" void kernel_launch(void* const* d_in, const int* in_sizes, int n_in,
                              void* d_out, int out_size) {
    const float* feats = (const float*)d_in[0];
    const int* memb = (const int*)d_in[1];
    float* out = (float*)d_out;

    const int n_atoms = in_sizes[1];      // 524288
    const int n4 = out_size / 4;          // 524288 float4

    gg_zero4_kernel<<<(n4 + 255) / 256, 256>>>((float4*)out, n4);

    // Contiguous span per warp, rounded up to a multiple of 32 rows.
    int rows_per_warp = (n_atoms + N_WARPS_TOTAL - 1) / N_WARPS_TOTAL;
    rows_per_warp = (rows_per_warp + 31) & ~31;   // 128 for 524288 atoms

    gg_segsum_kernel<<<N_BLOCKS, TPB>>>((const float4*)feats, memb, out,
                                        n_atoms, rows_per_warp);
}

// round 6
// speedup vs baseline: 1.0652x; 1.0652x over previous
#include <cuda_runtime.h>
#include <cuda_bf16.h>

// GraphGather / segment_sum:
//   out[b, :] = sum of feats[a, :] for membership[a] == b
// feats: [524288, 128] f32, membership: [524288] i32 (SORTED), out: [16384, 128] f32.
//
// R6 = R3 (best: 45.8us) with ONE change: boundary flushes use a single
// red.global.add.v4.f32 (16B vector reduction, sm_90+) per lane instead of
// 4 scalar atomicAdds -> 4x fewer atomic ops through LTS, better sector use.
//  - TPB=256, 2048 blocks, 32 rows/warp (proven geometry)
//  - float4 zero-fill kernel for the poisoned output
//  - one coalesced membership load per warp, shfl-distributed
//  - 4 batches of 8 unconditional LDG.E.128 (MLP_p1 = 8)

#define N_FEAT 128
#define FEAT4 (N_FEAT / 4)       // 32 float4 per row
#define ROWS_PER_WARP 32
#define TPB 256

__global__ void gg_zero4_kernel(float4* __restrict__ out, int n4) {
    int i = blockIdx.x * blockDim.x + threadIdx.x;
    if (i < n4) out[i] = make_float4(0.f, 0.f, 0.f, 0.f);
}

__device__ __forceinline__ void gg_flush(float* __restrict__ out,
                                         int seg, int lane, const float4& acc) {
    // out + seg*128 + lane*4 floats -> byte offset seg*512 + lane*16: 16B aligned.
    float* o = out + (size_t)seg * N_FEAT + lane * 4;
    asm volatile("red.global.add.v4.f32 [%0], {%1, %2, %3, %4};"
                 :: "l"(o), "f"(acc.x), "f"(acc.y), "f"(acc.z), "f"(acc.w)
                 : "memory");
}

__global__ __launch_bounds__(TPB)
void gg_segsum_kernel(const float4* __restrict__ feats,
                      const int* __restrict__ memb,
                      float* __restrict__ out,
                      int n_atoms) {
    const int warp_id = (blockIdx.x * TPB + threadIdx.x) >> 5;
    const int lane = threadIdx.x & 31;
    const unsigned FULL = 0xFFFFFFFFu;

    const int row0 = warp_id * ROWS_PER_WARP;
    if (row0 >= n_atoms) return;

    // One coalesced membership load for the warp's 32 rows.
    const int last = n_atoms - 1;
    int mrow = row0 + lane;
    int mlane = memb[mrow <= last ? mrow : last];

    const int nrows = (row0 + ROWS_PER_WARP <= n_atoms) ? ROWS_PER_WARP
                                                        : (n_atoms - row0);
    const float4* base = feats + (size_t)row0 * FEAT4 + lane;

    float4 acc = make_float4(0.f, 0.f, 0.f, 0.f);
    int cur = __shfl_sync(FULL, mlane, 0);

    if (nrows == ROWS_PER_WARP) {
        #pragma unroll
        for (int bt = 0; bt < 4; ++bt) {
            // 8 independent 128-bit loads, issued back-to-back (MLP_p1 = 8).
            float4 v[8];
            #pragma unroll
            for (int i = 0; i < 8; ++i)
                v[i] = __ldcs(base + (size_t)(bt * 8 + i) * FEAT4);

            #pragma unroll
            for (int i = 0; i < 8; ++i) {
                int m = __shfl_sync(FULL, mlane, bt * 8 + i);
                if (m != cur) {            // rare: ~1 boundary / warp
                    gg_flush(out, cur, lane, acc);
                    acc = make_float4(0.f, 0.f, 0.f, 0.f);
                    cur = m;
                }
                acc.x += v[i].x; acc.y += v[i].y;
                acc.z += v[i].z; acc.w += v[i].w;
            }
        }
    } else {
        for (int i = 0; i < nrows; ++i) {
            float4 v = __ldcs(base + (size_t)i * FEAT4);
            int m = __shfl_sync(FULL, mlane, i);
            if (m != cur) {
                gg_flush(out, cur, lane, acc);
                acc = make_float4(0.f, 0.f, 0.f, 0.f);
                cur = m;
            }
            acc.x += v.x; acc.y += v.y; acc.z += v.z; acc.w += v.w;
        }
    }

    gg_flush(out, cur, lane, acc);
}

extern "C" void kernel_launch(void* const* d_in, const int* in_sizes, int n_in,
                              void* d_out, int out_size) {
    const float* feats = (const float*)d_in[0];
    const int* memb = (const int*)d_in[1];
    float* out = (float*)d_out;

    const int n_atoms = in_sizes[1];      // 524288
    const int n4 = out_size / 4;          // 524288 float4

    gg_zero4_kernel<<<(n4 + 255) / 256, 256>>>((float4*)out, n4);

    const int n_warps = (n_atoms + ROWS_PER_WARP - 1) / ROWS_PER_WARP;
    const int blocks = (n_warps + (TPB / 32) - 1) / (TPB / 32);
    gg_segsum_kernel<<<blocks, TPB>>>((const float4*)feats, memb, out, n_atoms);
}

// round 7
// speedup vs baseline: 1.0756x; 1.0097x over previous
#include <cuda_runtime.h>
#include <cuda_bf16.h>

// GraphGather / segment_sum:
//   out[b, :] = sum of feats[a, :] for membership[a] == b
// feats: [524288, 128] f32, membership: [524288] i32 (SORTED), out: [16384, 128] f32.
//
// R7 = R6 segsum (best kernel: 44.2us, DRAM 81.2%) with the zero-fill kernel
// replaced by a cudaMemsetAsync graph node (f32 0.0 == all-zero bytes).
//  - TPB=256, 2048 blocks, 32 rows/warp (proven geometry)
//  - one coalesced membership load per warp, shfl-distributed
//  - 4 batches of 8 unconditional LDG.E.128 (MLP_p1 = 8), evict-first
//  - boundary flushes via red.global.add.v4.f32 (one 16B RMW per lane)

#define N_FEAT 128
#define FEAT4 (N_FEAT / 4)       // 32 float4 per row
#define ROWS_PER_WARP 32
#define TPB 256

__device__ __forceinline__ void gg_flush(float* __restrict__ out,
                                         int seg, int lane, const float4& acc) {
    // byte offset = seg*512 + lane*16 -> 16B aligned.
    float* o = out + (size_t)seg * N_FEAT + lane * 4;
    asm volatile("red.global.add.v4.f32 [%0], {%1, %2, %3, %4};"
                 :: "l"(o), "f"(acc.x), "f"(acc.y), "f"(acc.z), "f"(acc.w)
                 : "memory");
}

__global__ __launch_bounds__(TPB)
void gg_segsum_kernel(const float4* __restrict__ feats,
                      const int* __restrict__ memb,
                      float* __restrict__ out,
                      int n_atoms) {
    const int warp_id = (blockIdx.x * TPB + threadIdx.x) >> 5;
    const int lane = threadIdx.x & 31;
    const unsigned FULL = 0xFFFFFFFFu;

    const int row0 = warp_id * ROWS_PER_WARP;
    if (row0 >= n_atoms) return;

    // One coalesced membership load for the warp's 32 rows.
    const int last = n_atoms - 1;
    int mrow = row0 + lane;
    int mlane = memb[mrow <= last ? mrow : last];

    const int nrows = (row0 + ROWS_PER_WARP <= n_atoms) ? ROWS_PER_WARP
                                                        : (n_atoms - row0);
    const float4* base = feats + (size_t)row0 * FEAT4 + lane;

    float4 acc = make_float4(0.f, 0.f, 0.f, 0.f);
    int cur = __shfl_sync(FULL, mlane, 0);

    if (nrows == ROWS_PER_WARP) {
        #pragma unroll
        for (int bt = 0; bt < 4; ++bt) {
            // 8 independent 128-bit loads, issued back-to-back (MLP_p1 = 8).
            float4 v[8];
            #pragma unroll
            for (int i = 0; i < 8; ++i)
                v[i] = __ldcs(base + (size_t)(bt * 8 + i) * FEAT4);

            #pragma unroll
            for (int i = 0; i < 8; ++i) {
                int m = __shfl_sync(FULL, mlane, bt * 8 + i);
                if (m != cur) {            // rare: ~1 boundary / warp
                    gg_flush(out, cur, lane, acc);
                    acc = make_float4(0.f, 0.f, 0.f, 0.f);
                    cur = m;
                }
                acc.x += v[i].x; acc.y += v[i].y;
                acc.z += v[i].z; acc.w += v[i].w;
            }
        }
    } else {
        for (int i = 0; i < nrows; ++i) {
            float4 v = __ldcs(base + (size_t)i * FEAT4);
            int m = __shfl_sync(FULL, mlane, i);
            if (m != cur) {
                gg_flush(out, cur, lane, acc);
                acc = make_float4(0.f, 0.f, 0.f, 0.f);
                cur = m;
            }
            acc.x += v.x; acc.y += v.y; acc.z += v.z; acc.w += v.w;
        }
    }

    gg_flush(out, cur, lane, acc);
}

extern "C" void kernel_launch(void* const* d_in, const int* in_sizes, int n_in,
                              void* d_out, int out_size) {
    const float* feats = (const float*)d_in[0];
    const int* memb = (const int*)d_in[1];
    float* out = (float*)d_out;

    const int n_atoms = in_sizes[1];      // 524288

    // Zero the poisoned output via a graph memset node (f32 0.0 == 0x00000000).
    cudaMemsetAsync(out, 0, (size_t)out_size * sizeof(float));

    const int n_warps = (n_atoms + ROWS_PER_WARP - 1) / ROWS_PER_WARP;
    const int blocks = (n_warps + (TPB / 32) - 1) / (TPB / 32);
    gg_segsum_kernel<<<blocks, TPB>>>((const float4*)feats, memb, out, n_atoms);
}